// round 1
// baseline (speedup 1.0000x reference)
#include <cuda_runtime.h>
#include <math.h>

// Problem constants
#define BN 4
#define SN 4096
#define DN 512
#define MTOT (BN * SN)          // 16384
#define HALF_W 128              // (257-1)/2
#define TQ 32                   // queries per attention block
#define WTOT 288                // key span per tile: TQ + 2*HALF_W
#define NCHUNK 9                // 288 / 32 key chunks

// Scratch (no allocation allowed -> device globals)
__device__ float Qg[MTOT * DN];
__device__ float Kg[MTOT * DN];
__device__ float Vg[MTOT * DN];

// ---------------------------------------------------------------------------
// Kernel 1: QKV projection. C[m,n] = sum_k x[m,k] * W[k,n] + b[n]
// Grid: (MTOT/64, 24). blockIdx.y selects {Wq,Wk,Wv} x 8 column blocks.
// 64x64 tile, BK=16, 256 threads, 4x4 micro-tile.
// ---------------------------------------------------------------------------
__global__ __launch_bounds__(256) void qkv_gemm(
    const float* __restrict__ x,
    const float* __restrict__ Wq, const float* __restrict__ Wk, const float* __restrict__ Wv,
    const float* __restrict__ bq, const float* __restrict__ bk, const float* __restrict__ bv)
{
    __shared__ float As[16 * 64];   // [k][m]
    __shared__ float Bs[16 * 64];   // [k][n]

    const int t  = threadIdx.x;
    const int m0 = blockIdx.x * 64;
    const int nb = blockIdx.y;
    const int which = nb >> 3;
    const int nloc  = (nb & 7) * 64;

    const float* W    = (which == 0) ? Wq : (which == 1) ? Wk : Wv;
    const float* bias = (which == 0) ? bq : (which == 1) ? bk : bv;
    float*       C    = (which == 0) ? Qg : (which == 1) ? Kg : Vg;

    const int ty = t >> 4, tx = t & 15;
    const int arow = t >> 2, acv = t & 3;     // A tile loader: 64 rows x 4 float4
    const int brow = t >> 4, bcv = t & 15;    // B tile loader: 16 rows x 16 float4

    float acc[4][4];
    #pragma unroll
    for (int u = 0; u < 4; u++)
        #pragma unroll
        for (int v = 0; v < 4; v++) acc[u][v] = 0.f;

    for (int k0 = 0; k0 < DN; k0 += 16) {
        float4 av = *(const float4*)&x[(m0 + arow) * DN + k0 + acv * 4];
        As[(acv * 4 + 0) * 64 + arow] = av.x;
        As[(acv * 4 + 1) * 64 + arow] = av.y;
        As[(acv * 4 + 2) * 64 + arow] = av.z;
        As[(acv * 4 + 3) * 64 + arow] = av.w;
        *(float4*)&Bs[brow * 64 + bcv * 4] =
            *(const float4*)&W[(k0 + brow) * DN + nloc + bcv * 4];
        __syncthreads();

        #pragma unroll
        for (int k = 0; k < 16; k++) {
            float4 a4 = *(float4*)&As[k * 64 + ty * 4];
            float4 b4 = *(float4*)&Bs[k * 64 + tx * 4];
            acc[0][0] += a4.x * b4.x; acc[0][1] += a4.x * b4.y;
            acc[0][2] += a4.x * b4.z; acc[0][3] += a4.x * b4.w;
            acc[1][0] += a4.y * b4.x; acc[1][1] += a4.y * b4.y;
            acc[1][2] += a4.y * b4.z; acc[1][3] += a4.y * b4.w;
            acc[2][0] += a4.z * b4.x; acc[2][1] += a4.z * b4.y;
            acc[2][2] += a4.z * b4.z; acc[2][3] += a4.z * b4.w;
            acc[3][0] += a4.w * b4.x; acc[3][1] += a4.w * b4.y;
            acc[3][2] += a4.w * b4.z; acc[3][3] += a4.w * b4.w;
        }
        __syncthreads();
    }

    float4 bv4 = *(const float4*)&bias[nloc + tx * 4];
    #pragma unroll
    for (int u = 0; u < 4; u++) {
        float4 o;
        o.x = acc[u][0] + bv4.x;
        o.y = acc[u][1] + bv4.y;
        o.z = acc[u][2] + bv4.z;
        o.w = acc[u][3] + bv4.w;
        *(float4*)&C[(m0 + ty * 4 + u) * DN + nloc + tx * 4] = o;
    }
}

// ---------------------------------------------------------------------------
// Kernel 2: banded attention. One block = 32 queries of one batch.
// smem: Q tile (64KB) + K/V chunk (64KB, reused) + scores 32x288 (36KB).
// ---------------------------------------------------------------------------
#define ATTN_SMEM ((4096 + 4096) * 16 + TQ * WTOT * 4)   // 167936 bytes

__global__ __launch_bounds__(256, 1) void attn_kernel(float* __restrict__ out)
{
    extern __shared__ float sm[];
    float4* Qs4  = (float4*)sm;         // [32][128] float4, row-major
    float4* KVs4 = Qs4 + 4096;          // K: swizzled [dv][kj]; V: row-major [kj][dv]
    float*  Ps   = (float*)(KVs4 + 4096); // [32][288]

    const int t    = threadIdx.x;
    const int b    = blockIdx.x >> 7;          // 128 tiles per batch
    const int tile = blockIdx.x & 127;
    const int q0   = tile * TQ;
    const int base = b * SN;
    const int jb0  = q0 - HALF_W;

    const float4* Q4 = (const float4*)Qg;
    const float4* K4 = (const float4*)Kg;
    const float4* V4 = (const float4*)Vg;

    // Load Q tile (rows are contiguous in global memory)
    for (int idx = t; idx < TQ * 128; idx += 256)
        Qs4[idx] = Q4[(base + q0) * 128 + idx];

    const int warp = t >> 5, lane = t & 31;
    const int qi0  = warp * 4;
    const float scale = 0.044194173824159216f;   // 1/sqrt(512)

    // ---- Phase 1: scores. K chunk stored transposed+XOR-swizzled:
    //      KVs4[dv*32 + (kj ^ (dv&31))] = K[kj][4dv..4dv+3]
    for (int c = 0; c < NCHUNK; c++) {
        const int jb = jb0 + c * 32;
        __syncthreads();   // previous chunk's readers done
        for (int idx = t; idx < 4096; idx += 256) {
            int jj = idx >> 7, dv = idx & 127;
            int j = jb + jj;
            float4 v = make_float4(0.f, 0.f, 0.f, 0.f);
            if (j >= 0 && j < SN) v = K4[(base + j) * 128 + dv];
            KVs4[dv * 32 + (jj ^ (dv & 31))] = v;
        }
        __syncthreads();

        float acc0 = 0.f, acc1 = 0.f, acc2 = 0.f, acc3 = 0.f;
        #pragma unroll 4
        for (int dv = 0; dv < 128; dv++) {
            float4 k4 = KVs4[dv * 32 + (lane ^ (dv & 31))];
            float4 q;
            q = Qs4[(qi0 + 0) * 128 + dv];
            acc0 += q.x * k4.x + q.y * k4.y + q.z * k4.z + q.w * k4.w;
            q = Qs4[(qi0 + 1) * 128 + dv];
            acc1 += q.x * k4.x + q.y * k4.y + q.z * k4.z + q.w * k4.w;
            q = Qs4[(qi0 + 2) * 128 + dv];
            acc2 += q.x * k4.x + q.y * k4.y + q.z * k4.z + q.w * k4.w;
            q = Qs4[(qi0 + 3) * 128 + dv];
            acc3 += q.x * k4.x + q.y * k4.y + q.z * k4.z + q.w * k4.w;
        }
        Ps[(qi0 + 0) * WTOT + c * 32 + lane] = acc0 * scale;
        Ps[(qi0 + 1) * WTOT + c * 32 + lane] = acc1 * scale;
        Ps[(qi0 + 2) * WTOT + c * 32 + lane] = acc2 * scale;
        Ps[(qi0 + 3) * WTOT + c * 32 + lane] = acc3 * scale;
    }
    __syncthreads();

    // ---- Phase 2: softmax per query row over its valid band
    for (int row = warp; row < TQ; row += 8) {
        const int lo = row, hi = row + 256;
        float m = -1e30f;
        #pragma unroll
        for (int tt = 0; tt < 9; tt++) {
            int kk = lane + tt * 32;
            int j = jb0 + kk;
            bool valid = (kk >= lo) && (kk <= hi) && (j >= 0) && (j < SN);
            float s = Ps[row * WTOT + kk];
            if (valid) m = fmaxf(m, s);
        }
        #pragma unroll
        for (int off = 16; off; off >>= 1)
            m = fmaxf(m, __shfl_xor_sync(0xffffffffu, m, off));
        float sum = 0.f;
        #pragma unroll
        for (int tt = 0; tt < 9; tt++) {
            int kk = lane + tt * 32;
            int j = jb0 + kk;
            bool valid = (kk >= lo) && (kk <= hi) && (j >= 0) && (j < SN);
            float p = valid ? __expf(Ps[row * WTOT + kk] - m) : 0.f;
            Ps[row * WTOT + kk] = p;
            sum += p;
        }
        #pragma unroll
        for (int off = 16; off; off >>= 1)
            sum += __shfl_xor_sync(0xffffffffu, sum, off);
        float inv = 1.f / sum;
        #pragma unroll
        for (int tt = 0; tt < 9; tt++) {
            int kk = lane + tt * 32;
            Ps[row * WTOT + kk] *= inv;
        }
    }
    __syncthreads();

    // ---- Phase 3: O = P @ V. Thread owns (qi, 64 strided d values).
    const int qi = t >> 3, dl = t & 7;
    float4 acc4[16];
    #pragma unroll
    for (int dd = 0; dd < 16; dd++) acc4[dd] = make_float4(0.f, 0.f, 0.f, 0.f);

    for (int c = 0; c < NCHUNK; c++) {
        const int jb = jb0 + c * 32;
        __syncthreads();   // previous chunk's readers done
        for (int idx = t; idx < 4096; idx += 256) {
            int jj = idx >> 7, dv = idx & 127;
            int j = jb + jj;
            float4 v = make_float4(0.f, 0.f, 0.f, 0.f);
            if (j >= 0 && j < SN) v = V4[(base + j) * 128 + dv];
            KVs4[jj * 128 + dv] = v;   // row-major, conflict-free
        }
        __syncthreads();

        for (int kj = 0; kj < 32; kj++) {
            float w = Ps[qi * WTOT + c * 32 + kj];
            #pragma unroll
            for (int dd = 0; dd < 16; dd++) {
                float4 v = KVs4[kj * 128 + dl + 8 * dd];
                acc4[dd].x += w * v.x;
                acc4[dd].y += w * v.y;
                acc4[dd].z += w * v.z;
                acc4[dd].w += w * v.w;
            }
        }
    }

    float4* O4 = (float4*)out;
    #pragma unroll
    for (int dd = 0; dd < 16; dd++)
        O4[(base + q0 + qi) * 128 + dl + 8 * dd] = acc4[dd];
}

// ---------------------------------------------------------------------------
extern "C" void kernel_launch(void* const* d_in, const int* in_sizes, int n_in,
                              void* d_out, int out_size)
{
    const float* x  = (const float*)d_in[0];
    const float* Wq = (const float*)d_in[1];
    const float* bq = (const float*)d_in[2];
    const float* Wk = (const float*)d_in[3];
    const float* bk = (const float*)d_in[4];
    const float* Wv = (const float*)d_in[5];
    const float* bv = (const float*)d_in[6];
    float* out = (float*)d_out;

    cudaFuncSetAttribute(attn_kernel,
                         cudaFuncAttributeMaxDynamicSharedMemorySize, ATTN_SMEM);

    qkv_gemm<<<dim3(MTOT / 64, 24), 256>>>(x, Wq, Wk, Wv, bq, bk, bv);
    attn_kernel<<<BN * (SN / TQ), 256, ATTN_SMEM>>>(out);
}

// round 3
// speedup vs baseline: 2.3539x; 2.3539x over previous
#include <cuda_runtime.h>
#include <math.h>

#define BN 4
#define SN 4096
#define DN 512
#define MTOT (BN * SN)          // 16384
#define HALF_W 128
#define TQ 32
#define SPAN 288                // TQ + 2*HALF_W
#define PS_STRIDE 296           // padded score-row stride (bank-friendly)

// Scratch (no allocation allowed -> device globals)
__device__ float Qg[MTOT * DN];
__device__ float Kg[MTOT * DN];
__device__ float Vg[MTOT * DN];

// ---------------------------------------------------------------------------
// TF32 helpers
// ---------------------------------------------------------------------------
__device__ __forceinline__ unsigned f2tf(float f) {
    unsigned u;
    asm("cvt.rna.tf32.f32 %0, %1;" : "=r"(u) : "f"(f));
    return u;
}

__device__ __forceinline__ void mma_tf32(float* d, const unsigned* a, const unsigned* b) {
    asm volatile(
        "mma.sync.aligned.m16n8k8.row.col.f32.tf32.tf32.f32 "
        "{%0,%1,%2,%3}, {%4,%5,%6,%7}, {%8,%9}, {%0,%1,%2,%3};"
        : "+f"(d[0]), "+f"(d[1]), "+f"(d[2]), "+f"(d[3])
        : "r"(a[0]), "r"(a[1]), "r"(a[2]), "r"(a[3]),
          "r"(b[0]), "r"(b[1]));
}

// ---------------------------------------------------------------------------
// Kernel 1: QKV projection with TF32 tensor cores.
// C[m,n] = sum_k x[m,k]*W[k,n] + b[n].  Block tile 128m x 128n, k-chunk 32.
// 8 warps, warp tile 64m x 32n (4 m16-frags x 4 n8-frags).
// Grid: (128, 12): y -> {Wq,Wk,Wv} x 4 n-blocks.
// ---------------------------------------------------------------------------
#define AS_STRIDE 36    // 128 rows x 36 (padded from 32): frag loads conflict-free
#define BS_STRIDE 136   // 32 rows x 136 (padded from 128)

__global__ __launch_bounds__(256) void qkv_mma(
    const float* __restrict__ x,
    const float* __restrict__ Wq, const float* __restrict__ Wk, const float* __restrict__ Wv,
    const float* __restrict__ bq, const float* __restrict__ bk, const float* __restrict__ bv)
{
    __shared__ unsigned As[128 * AS_STRIDE];   // x tile (tf32 bits), row-major [m][k]
    __shared__ unsigned Bs[32 * BS_STRIDE];    // W tile (tf32 bits), row-major [k][n]

    const int t  = threadIdx.x;
    const int m0 = blockIdx.x * 128;
    const int yb = blockIdx.y;
    const int which = yb >> 2;
    const int n0 = (yb & 3) * 128;

    const float* W    = (which == 0) ? Wq : (which == 1) ? Wk : Wv;
    const float* bias = (which == 0) ? bq : (which == 1) ? bk : bv;
    float*       C    = (which == 0) ? Qg : (which == 1) ? Kg : Vg;

    const int warp = t >> 5, lane = t & 31;
    const int wm = (warp & 1) * 64;
    const int wn = (warp >> 1) * 32;
    const int gid = lane >> 2, tig = lane & 3;

    float d[4][4][4];
    #pragma unroll
    for (int mt = 0; mt < 4; mt++)
        #pragma unroll
        for (int nt = 0; nt < 4; nt++)
            #pragma unroll
            for (int r = 0; r < 4; r++) d[mt][nt][r] = 0.f;

    for (int k0 = 0; k0 < DN; k0 += 32) {
        __syncthreads();
        // Load A tile 128x32 (coalesced float4, convert to tf32 bits)
        #pragma unroll
        for (int i = 0; i < 4; i++) {
            int idx = t + 256 * i;
            int m = idx >> 3, c = idx & 7;
            float4 v = *(const float4*)&x[(m0 + m) * DN + k0 + 4 * c];
            unsigned* p = &As[m * AS_STRIDE + 4 * c];
            p[0] = f2tf(v.x); p[1] = f2tf(v.y); p[2] = f2tf(v.z); p[3] = f2tf(v.w);
        }
        // Load B tile 32x128
        #pragma unroll
        for (int i = 0; i < 4; i++) {
            int idx = t + 256 * i;
            int k = idx >> 5, c = idx & 31;
            float4 v = *(const float4*)&W[(k0 + k) * DN + n0 + 4 * c];
            unsigned* p = &Bs[k * BS_STRIDE + 4 * c];
            p[0] = f2tf(v.x); p[1] = f2tf(v.y); p[2] = f2tf(v.z); p[3] = f2tf(v.w);
        }
        __syncthreads();

        #pragma unroll
        for (int kt = 0; kt < 4; kt++) {
            unsigned af[4][4], bf[4][2];
            #pragma unroll
            for (int mt = 0; mt < 4; mt++) {
                int r = wm + 16 * mt + gid;
                af[mt][0] = As[r * AS_STRIDE + 8 * kt + tig];
                af[mt][1] = As[(r + 8) * AS_STRIDE + 8 * kt + tig];
                af[mt][2] = As[r * AS_STRIDE + 8 * kt + 4 + tig];
                af[mt][3] = As[(r + 8) * AS_STRIDE + 8 * kt + 4 + tig];
            }
            #pragma unroll
            for (int nt = 0; nt < 4; nt++) {
                int cn = wn + 8 * nt + gid;
                bf[nt][0] = Bs[(8 * kt + tig) * BS_STRIDE + cn];
                bf[nt][1] = Bs[(8 * kt + 4 + tig) * BS_STRIDE + cn];
            }
            #pragma unroll
            for (int mt = 0; mt < 4; mt++)
                #pragma unroll
                for (int nt = 0; nt < 4; nt++)
                    mma_tf32(d[mt][nt], af[mt], bf[nt]);
        }
    }

    // Epilogue: add bias, store
    #pragma unroll
    for (int mt = 0; mt < 4; mt++) {
        int r = m0 + wm + 16 * mt + gid;
        #pragma unroll
        for (int nt = 0; nt < 4; nt++) {
            int cn = n0 + wn + 8 * nt + 2 * tig;
            float b0v = bias[cn], b1v = bias[cn + 1];
            float2 o0 = make_float2(d[mt][nt][0] + b0v, d[mt][nt][1] + b1v);
            float2 o1 = make_float2(d[mt][nt][2] + b0v, d[mt][nt][3] + b1v);
            *(float2*)&C[r * DN + cn]       = o0;
            *(float2*)&C[(r + 8) * DN + cn] = o1;
        }
    }
}

// ---------------------------------------------------------------------------
// Kernel 2: banded attention, 32 queries/block, 288 threads (9 warps), 2 CTA/SM.
// smem layout (floats):
//   [0,1024)              Qt  [k=32][q=32]
//   [1024, 1024+9216)     Kt  [k=32][key=288]
//   [10240, 10240+9472)   Ps  [q=32][PS_STRIDE=296]
// Phase 3 aliases Vs4 = [key=16][128] float4 = 8192 floats at offset 0
// (over Qt+Kt, both dead); Ps at float offset 10240 > 8192 is untouched.
// ---------------------------------------------------------------------------
#define ATTN_THREADS 288
#define ATTN_SMEM ((1024 + 32 * SPAN + TQ * PS_STRIDE) * 4)   // 78848 bytes

__global__ __launch_bounds__(ATTN_THREADS, 2) void attn_kernel(float* __restrict__ out)
{
    extern __shared__ float sm[];
    float*  Qt  = sm;                          // [k=32][q=32]
    float*  Kt  = sm + 1024;                   // [k=32][key=288]
    float*  Ps  = sm + 1024 + 32 * SPAN;       // [q=32][PS_STRIDE]
    float4* Vs4 = (float4*)sm;                 // [key=16][128], phase 3 only

    const int t    = threadIdx.x;
    const int b    = blockIdx.x >> 7;
    const int tile = blockIdx.x & 127;
    const int q0   = tile * TQ;
    const int base = b * SN;
    const int jb0  = q0 - HALF_W;

    const float4* Q4 = (const float4*)Qg;
    const float4* K4 = (const float4*)Kg;
    const float4* V4 = (const float4*)Vg;

    const int warp = t >> 5, lane = t & 31;
    const int qg = t & 7;        // query group (4 queries)
    const int kg = t >> 3;       // key group 0..35 (8 keys)
    const float scale = 0.044194173824159216f;   // 1/sqrt(512)

    float acc[4][8];
    #pragma unroll
    for (int i = 0; i < 4; i++)
        #pragma unroll
        for (int j = 0; j < 8; j++) acc[i][j] = 0.f;

    // ---- Phase 1: S = Q K^T over k-chunks of 32 dims
    for (int kc = 0; kc < 16; kc++) {
        __syncthreads();
        // Qt: transpose-load 32 queries x 32 dims
        if (t < 256) {
            int q = t >> 3, c = t & 7;
            float4 v = Q4[(base + q0 + q) * 128 + kc * 8 + c];
            Qt[(4 * c + 0) * 32 + q] = v.x;
            Qt[(4 * c + 1) * 32 + q] = v.y;
            Qt[(4 * c + 2) * 32 + q] = v.z;
            Qt[(4 * c + 3) * 32 + q] = v.w;
        }
        // Kt: transpose-load 288 keys x 32 dims via 4x4 register tiles
        #pragma unroll
        for (int i = 0; i < 2; i++) {
            int idx = t + ATTN_THREADS * i;      // 0..575
            int jb = idx % 72;                   // 4-key block
            int dq = idx / 72;                   // float4-dim block 0..7
            float4 v0 = make_float4(0.f,0.f,0.f,0.f), v1 = v0, v2 = v0, v3 = v0;
            int j0 = jb0 + 4 * jb;
            if (j0 + 0 >= 0 && j0 + 0 < SN) v0 = K4[(base + j0 + 0) * 128 + kc * 8 + dq];
            if (j0 + 1 >= 0 && j0 + 1 < SN) v1 = K4[(base + j0 + 1) * 128 + kc * 8 + dq];
            if (j0 + 2 >= 0 && j0 + 2 < SN) v2 = K4[(base + j0 + 2) * 128 + kc * 8 + dq];
            if (j0 + 3 >= 0 && j0 + 3 < SN) v3 = K4[(base + j0 + 3) * 128 + kc * 8 + dq];
            float* kr = &Kt[(4 * dq) * SPAN + 4 * jb];
            *(float4*)&kr[0 * SPAN] = make_float4(v0.x, v1.x, v2.x, v3.x);
            *(float4*)&kr[1 * SPAN] = make_float4(v0.y, v1.y, v2.y, v3.y);
            *(float4*)&kr[2 * SPAN] = make_float4(v0.z, v1.z, v2.z, v3.z);
            *(float4*)&kr[3 * SPAN] = make_float4(v0.w, v1.w, v2.w, v3.w);
        }
        __syncthreads();

        #pragma unroll 8
        for (int k = 0; k < 32; k++) {
            float4 qv = *(float4*)&Qt[k * 32 + qg * 4];
            float4 ka = *(float4*)&Kt[k * SPAN + kg * 8];
            float4 kb = *(float4*)&Kt[k * SPAN + kg * 8 + 4];
            acc[0][0] += qv.x * ka.x; acc[0][1] += qv.x * ka.y;
            acc[0][2] += qv.x * ka.z; acc[0][3] += qv.x * ka.w;
            acc[0][4] += qv.x * kb.x; acc[0][5] += qv.x * kb.y;
            acc[0][6] += qv.x * kb.z; acc[0][7] += qv.x * kb.w;
            acc[1][0] += qv.y * ka.x; acc[1][1] += qv.y * ka.y;
            acc[1][2] += qv.y * ka.z; acc[1][3] += qv.y * ka.w;
            acc[1][4] += qv.y * kb.x; acc[1][5] += qv.y * kb.y;
            acc[1][6] += qv.y * kb.z; acc[1][7] += qv.y * kb.w;
            acc[2][0] += qv.z * ka.x; acc[2][1] += qv.z * ka.y;
            acc[2][2] += qv.z * ka.z; acc[2][3] += qv.z * ka.w;
            acc[2][4] += qv.z * kb.x; acc[2][5] += qv.z * kb.y;
            acc[2][6] += qv.z * kb.z; acc[2][7] += qv.z * kb.w;
            acc[3][0] += qv.w * ka.x; acc[3][1] += qv.w * ka.y;
            acc[3][2] += qv.w * ka.z; acc[3][3] += qv.w * ka.w;
            acc[3][4] += qv.w * kb.x; acc[3][5] += qv.w * kb.y;
            acc[3][6] += qv.w * kb.z; acc[3][7] += qv.w * kb.w;
        }
    }

    // Store scores
    #pragma unroll
    for (int i = 0; i < 4; i++)
        #pragma unroll
        for (int j = 0; j < 8; j++)
            Ps[(qg * 4 + i) * PS_STRIDE + kg * 8 + j] = acc[i][j] * scale;
    __syncthreads();

    // ---- Phase 2: softmax per query row over its valid band
    for (int row = warp; row < TQ; row += 9) {
        const int lo = row, hi = row + 256;
        float m = -1e30f;
        #pragma unroll
        for (int tt = 0; tt < 9; tt++) {
            int kk = lane + tt * 32;
            int j = jb0 + kk;
            bool valid = (kk >= lo) && (kk <= hi) && (j >= 0) && (j < SN);
            float s = Ps[row * PS_STRIDE + kk];
            if (valid) m = fmaxf(m, s);
        }
        #pragma unroll
        for (int off = 16; off; off >>= 1)
            m = fmaxf(m, __shfl_xor_sync(0xffffffffu, m, off));
        float sum = 0.f;
        #pragma unroll
        for (int tt = 0; tt < 9; tt++) {
            int kk = lane + tt * 32;
            int j = jb0 + kk;
            bool valid = (kk >= lo) && (kk <= hi) && (j >= 0) && (j < SN);
            float p = valid ? __expf(Ps[row * PS_STRIDE + kk] - m) : 0.f;
            Ps[row * PS_STRIDE + kk] = p;
            sum += p;
        }
        #pragma unroll
        for (int off = 16; off; off >>= 1)
            sum += __shfl_xor_sync(0xffffffffu, sum, off);
        float inv = 1.f / sum;
        #pragma unroll
        for (int tt = 0; tt < 9; tt++) {
            int kk = lane + tt * 32;
            Ps[row * PS_STRIDE + kk] *= inv;
        }
    }

    // ---- Phase 3: O = P @ V over 18 chunks of 16 keys.
    // Vs4 = [16][128] float4 = 32768 B at smem offset 0 (< Ps offset 40960 B).
    const int qp = t >> 4;     // query pair 0..15 (valid when t<256)
    const int dl = t & 15;     // dim lane
    float4 av[2][8];
    #pragma unroll
    for (int i = 0; i < 2; i++)
        #pragma unroll
        for (int dd = 0; dd < 8; dd++) av[i][dd] = make_float4(0.f, 0.f, 0.f, 0.f);

    for (int c = 0; c < 18; c++) {
        const int jb = jb0 + c * 16;
        __syncthreads();
        for (int idx = t; idx < 2048; idx += ATTN_THREADS) {
            int jj = idx >> 7, dv = idx & 127;
            int j = jb + jj;
            float4 v = make_float4(0.f, 0.f, 0.f, 0.f);
            if (j >= 0 && j < SN) v = V4[(base + j) * 128 + dv];
            Vs4[jj * 128 + dv] = v;
        }
        __syncthreads();

        if (t < 256) {
            #pragma unroll 4
            for (int kj = 0; kj < 16; kj++) {
                float w0 = Ps[(2 * qp + 0) * PS_STRIDE + c * 16 + kj];
                float w1 = Ps[(2 * qp + 1) * PS_STRIDE + c * 16 + kj];
                #pragma unroll
                for (int dd = 0; dd < 8; dd++) {
                    float4 v = Vs4[kj * 128 + dl + 16 * dd];
                    av[0][dd].x += w0 * v.x; av[0][dd].y += w0 * v.y;
                    av[0][dd].z += w0 * v.z; av[0][dd].w += w0 * v.w;
                    av[1][dd].x += w1 * v.x; av[1][dd].y += w1 * v.y;
                    av[1][dd].z += w1 * v.z; av[1][dd].w += w1 * v.w;
                }
            }
        }
    }

    if (t < 256) {
        float4* O4 = (float4*)out;
        #pragma unroll
        for (int dd = 0; dd < 8; dd++) {
            O4[(base + q0 + 2 * qp + 0) * 128 + dl + 16 * dd] = av[0][dd];
            O4[(base + q0 + 2 * qp + 1) * 128 + dl + 16 * dd] = av[1][dd];
        }
    }
}

// ---------------------------------------------------------------------------
extern "C" void kernel_launch(void* const* d_in, const int* in_sizes, int n_in,
                              void* d_out, int out_size)
{
    const float* x  = (const float*)d_in[0];
    const float* Wq = (const float*)d_in[1];
    const float* bq = (const float*)d_in[2];
    const float* Wk = (const float*)d_in[3];
    const float* bk = (const float*)d_in[4];
    const float* Wv = (const float*)d_in[5];
    const float* bv = (const float*)d_in[6];
    float* out = (float*)d_out;

    cudaFuncSetAttribute(attn_kernel,
                         cudaFuncAttributeMaxDynamicSharedMemorySize, ATTN_SMEM);

    qkv_mma<<<dim3(MTOT / 128, 12), 256>>>(x, Wq, Wk, Wv, bq, bk, bv);
    attn_kernel<<<BN * (SN / TQ), ATTN_THREADS, ATTN_SMEM>>>(out);
}

// round 4
// speedup vs baseline: 2.9373x; 1.2479x over previous
#include <cuda_runtime.h>
#include <math.h>

#define BN 4
#define SN 4096
#define DN 512
#define MTOT (BN * SN)          // 16384
#define HALF_W 128
#define TQ 32
#define SPAN 288                // TQ + 2*HALF_W
#define PS_STRIDE 292           // 4 mod 32 -> conflict-free strided row access

// Scratch (no allocation allowed -> device globals)
__device__ float Qg[MTOT * DN];
__device__ float Kg[MTOT * DN];
__device__ float Vg[MTOT * DN];

// ---------------------------------------------------------------------------
// TF32 helpers
// ---------------------------------------------------------------------------
__device__ __forceinline__ unsigned f2tf(float f) {
    unsigned u;
    asm("cvt.rna.tf32.f32 %0, %1;" : "=r"(u) : "f"(f));
    return u;
}

__device__ __forceinline__ void mma_tf32(float* d, const unsigned* a, const unsigned* b) {
    asm volatile(
        "mma.sync.aligned.m16n8k8.row.col.f32.tf32.tf32.f32 "
        "{%0,%1,%2,%3}, {%4,%5,%6,%7}, {%8,%9}, {%0,%1,%2,%3};"
        : "+f"(d[0]), "+f"(d[1]), "+f"(d[2]), "+f"(d[3])
        : "r"(a[0]), "r"(a[1]), "r"(a[2]), "r"(a[3]),
          "r"(b[0]), "r"(b[1]));
}

// ---------------------------------------------------------------------------
// Kernel 1: QKV projection with TF32 tensor cores (unchanged from R3).
// ---------------------------------------------------------------------------
#define AS_STRIDE 36
#define BS_STRIDE 136

__global__ __launch_bounds__(256) void qkv_mma(
    const float* __restrict__ x,
    const float* __restrict__ Wq, const float* __restrict__ Wk, const float* __restrict__ Wv,
    const float* __restrict__ bq, const float* __restrict__ bk, const float* __restrict__ bv)
{
    __shared__ unsigned As[128 * AS_STRIDE];   // x tile (tf32 bits), row-major [m][k]
    __shared__ unsigned Bs[32 * BS_STRIDE];    // W tile (tf32 bits), row-major [k][n]

    const int t  = threadIdx.x;
    const int m0 = blockIdx.x * 128;
    const int yb = blockIdx.y;
    const int which = yb >> 2;
    const int n0 = (yb & 3) * 128;

    const float* W    = (which == 0) ? Wq : (which == 1) ? Wk : Wv;
    const float* bias = (which == 0) ? bq : (which == 1) ? bk : bv;
    float*       C    = (which == 0) ? Qg : (which == 1) ? Kg : Vg;

    const int warp = t >> 5, lane = t & 31;
    const int wm = (warp & 1) * 64;
    const int wn = (warp >> 1) * 32;
    const int gid = lane >> 2, tig = lane & 3;

    float d[4][4][4];
    #pragma unroll
    for (int mt = 0; mt < 4; mt++)
        #pragma unroll
        for (int nt = 0; nt < 4; nt++)
            #pragma unroll
            for (int r = 0; r < 4; r++) d[mt][nt][r] = 0.f;

    for (int k0 = 0; k0 < DN; k0 += 32) {
        __syncthreads();
        #pragma unroll
        for (int i = 0; i < 4; i++) {
            int idx = t + 256 * i;
            int m = idx >> 3, c = idx & 7;
            float4 v = *(const float4*)&x[(m0 + m) * DN + k0 + 4 * c];
            unsigned* p = &As[m * AS_STRIDE + 4 * c];
            p[0] = f2tf(v.x); p[1] = f2tf(v.y); p[2] = f2tf(v.z); p[3] = f2tf(v.w);
        }
        #pragma unroll
        for (int i = 0; i < 4; i++) {
            int idx = t + 256 * i;
            int k = idx >> 5, c = idx & 31;
            float4 v = *(const float4*)&W[(k0 + k) * DN + n0 + 4 * c];
            unsigned* p = &Bs[k * BS_STRIDE + 4 * c];
            p[0] = f2tf(v.x); p[1] = f2tf(v.y); p[2] = f2tf(v.z); p[3] = f2tf(v.w);
        }
        __syncthreads();

        #pragma unroll
        for (int kt = 0; kt < 4; kt++) {
            unsigned af[4][4], bf[4][2];
            #pragma unroll
            for (int mt = 0; mt < 4; mt++) {
                int r = wm + 16 * mt + gid;
                af[mt][0] = As[r * AS_STRIDE + 8 * kt + tig];
                af[mt][1] = As[(r + 8) * AS_STRIDE + 8 * kt + tig];
                af[mt][2] = As[r * AS_STRIDE + 8 * kt + 4 + tig];
                af[mt][3] = As[(r + 8) * AS_STRIDE + 8 * kt + 4 + tig];
            }
            #pragma unroll
            for (int nt = 0; nt < 4; nt++) {
                int cn = wn + 8 * nt + gid;
                bf[nt][0] = Bs[(8 * kt + tig) * BS_STRIDE + cn];
                bf[nt][1] = Bs[(8 * kt + 4 + tig) * BS_STRIDE + cn];
            }
            #pragma unroll
            for (int mt = 0; mt < 4; mt++)
                #pragma unroll
                for (int nt = 0; nt < 4; nt++)
                    mma_tf32(d[mt][nt], af[mt], bf[nt]);
        }
    }

    #pragma unroll
    for (int mt = 0; mt < 4; mt++) {
        int r = m0 + wm + 16 * mt + gid;
        #pragma unroll
        for (int nt = 0; nt < 4; nt++) {
            int cn = n0 + wn + 8 * nt + 2 * tig;
            float b0v = bias[cn], b1v = bias[cn + 1];
            float2 o0 = make_float2(d[mt][nt][0] + b0v, d[mt][nt][1] + b1v);
            float2 o1 = make_float2(d[mt][nt][2] + b0v, d[mt][nt][3] + b1v);
            *(float2*)&C[r * DN + cn]       = o0;
            *(float2*)&C[(r + 8) * DN + cn] = o1;
        }
    }
}

// ---------------------------------------------------------------------------
// Kernel 2: banded attention. 288 threads (9 warps), 2 CTA/SM.
// Phase 1: S = Q K^T via TF32 mma. Warp w owns keys [w*32, w*32+32).
// smem layout (floats):
//   [0, 1152)           Qs  [q=32][36]   (tf32 bits)
//   [1152, 11520)       Ks  [key=288][36] (tf32 bits)
//   [11520, 20864)      Ps  [q=32][292]
// Phase 3 aliases Vs4 [16][128] float4 (32768 B) at offset 0 (< Ps@46080 B).
// ---------------------------------------------------------------------------
#define QS_STRIDE 36
#define KS_STRIDE 36
#define ATTN_THREADS 288
#define ATTN_SMEM ((1152 + 288 * KS_STRIDE + TQ * PS_STRIDE) * 4)   // 83456 B

__global__ __launch_bounds__(ATTN_THREADS, 2) void attn_kernel(float* __restrict__ out)
{
    extern __shared__ float sm[];
    unsigned* Qsu = (unsigned*)sm;                    // [32][36]
    unsigned* Ksu = (unsigned*)(sm + 1152);           // [288][36]
    float*    Ps  = sm + 1152 + 288 * KS_STRIDE;      // [32][292]
    float4*   Vs4 = (float4*)sm;                      // [16][128], phase 3 only

    const int t    = threadIdx.x;
    const int b    = blockIdx.x >> 7;
    const int tile = blockIdx.x & 127;
    const int q0   = tile * TQ;
    const int base = b * SN;
    const int jb0  = q0 - HALF_W;

    const float4* Q4 = (const float4*)Qg;
    const float4* K4 = (const float4*)Kg;
    const float4* V4 = (const float4*)Vg;

    const int warp = t >> 5, lane = t & 31;
    const int gid = lane >> 2, tig = lane & 3;
    const float scale = 0.044194173824159216f;   // 1/sqrt(512)

    // Phase-1 accumulators: 2 m-frags (32 q) x 4 n-frags (32 keys owned by warp)
    float d[2][4][4];
    #pragma unroll
    for (int mt = 0; mt < 2; mt++)
        #pragma unroll
        for (int nf = 0; nf < 4; nf++)
            #pragma unroll
            for (int r = 0; r < 4; r++) d[mt][nf][r] = 0.f;

    // ---- Phase 1: S = Q K^T over 16 k-chunks of 32 dims
    for (int kc = 0; kc < 16; kc++) {
        __syncthreads();
        // Q chunk: 32 q x 32 dims, natural row-major (no transpose)
        if (t < 256) {
            int q = t >> 3, c = t & 7;
            float4 v = Q4[(base + q0 + q) * 128 + kc * 8 + c];
            unsigned* p = &Qsu[q * QS_STRIDE + 4 * c];
            p[0] = f2tf(v.x); p[1] = f2tf(v.y); p[2] = f2tf(v.z); p[3] = f2tf(v.w);
        }
        // K chunk: 288 keys x 32 dims, natural row-major, zero-fill OOB
        #pragma unroll
        for (int i = 0; i < 8; i++) {
            int idx = t + ATTN_THREADS * i;     // 0..2303
            int key = idx >> 3, c = idx & 7;
            int j = jb0 + key;
            float4 v = make_float4(0.f, 0.f, 0.f, 0.f);
            if (j >= 0 && j < SN) v = K4[(base + j) * 128 + kc * 8 + c];
            unsigned* p = &Ksu[key * KS_STRIDE + 4 * c];
            p[0] = f2tf(v.x); p[1] = f2tf(v.y); p[2] = f2tf(v.z); p[3] = f2tf(v.w);
        }
        __syncthreads();

        #pragma unroll
        for (int kt = 0; kt < 4; kt++) {
            unsigned af[2][4], bf[4][2];
            #pragma unroll
            for (int mt = 0; mt < 2; mt++) {
                int r = 16 * mt + gid;
                af[mt][0] = Qsu[r * QS_STRIDE + 8 * kt + tig];
                af[mt][1] = Qsu[(r + 8) * QS_STRIDE + 8 * kt + tig];
                af[mt][2] = Qsu[r * QS_STRIDE + 8 * kt + 4 + tig];
                af[mt][3] = Qsu[(r + 8) * QS_STRIDE + 8 * kt + 4 + tig];
            }
            #pragma unroll
            for (int nf = 0; nf < 4; nf++) {
                int key = warp * 32 + 8 * nf + gid;
                bf[nf][0] = Ksu[key * KS_STRIDE + 8 * kt + tig];
                bf[nf][1] = Ksu[key * KS_STRIDE + 8 * kt + 4 + tig];
            }
            #pragma unroll
            for (int mt = 0; mt < 2; mt++)
                #pragma unroll
                for (int nf = 0; nf < 4; nf++)
                    mma_tf32(d[mt][nf], af[mt], bf[nf]);
        }
    }

    // Store scores to Ps
    #pragma unroll
    for (int mt = 0; mt < 2; mt++)
        #pragma unroll
        for (int nf = 0; nf < 4; nf++) {
            int col = warp * 32 + 8 * nf + 2 * tig;
            int r0 = 16 * mt + gid, r1 = r0 + 8;
            *(float2*)&Ps[r0 * PS_STRIDE + col] =
                make_float2(d[mt][nf][0] * scale, d[mt][nf][1] * scale);
            *(float2*)&Ps[r1 * PS_STRIDE + col] =
                make_float2(d[mt][nf][2] * scale, d[mt][nf][3] * scale);
        }
    __syncthreads();

    // ---- Phase 2: softmax per query row over its valid band
    for (int row = warp; row < TQ; row += 9) {
        const int lo = row, hi = row + 256;
        float m = -1e30f;
        #pragma unroll
        for (int tt = 0; tt < 9; tt++) {
            int kk = lane + tt * 32;
            int j = jb0 + kk;
            bool valid = (kk >= lo) && (kk <= hi) && (j >= 0) && (j < SN);
            float s = Ps[row * PS_STRIDE + kk];
            if (valid) m = fmaxf(m, s);
        }
        #pragma unroll
        for (int off = 16; off; off >>= 1)
            m = fmaxf(m, __shfl_xor_sync(0xffffffffu, m, off));
        float sum = 0.f;
        #pragma unroll
        for (int tt = 0; tt < 9; tt++) {
            int kk = lane + tt * 32;
            int j = jb0 + kk;
            bool valid = (kk >= lo) && (kk <= hi) && (j >= 0) && (j < SN);
            float p = valid ? __expf(Ps[row * PS_STRIDE + kk] - m) : 0.f;
            Ps[row * PS_STRIDE + kk] = p;
            sum += p;
        }
        #pragma unroll
        for (int off = 16; off; off >>= 1)
            sum += __shfl_xor_sync(0xffffffffu, sum, off);
        float inv = 1.f / sum;
        #pragma unroll
        for (int tt = 0; tt < 9; tt++) {
            int kk = lane + tt * 32;
            Ps[row * PS_STRIDE + kk] *= inv;
        }
    }

    // ---- Phase 3: O = P @ V over 18 chunks of 16 keys (fp32 FFMA).
    const int qp = t >> 4;     // query pair 0..15 (valid when t<256)
    const int dl = t & 15;     // dim lane
    float4 av[2][8];
    #pragma unroll
    for (int i = 0; i < 2; i++)
        #pragma unroll
        for (int dd = 0; dd < 8; dd++) av[i][dd] = make_float4(0.f, 0.f, 0.f, 0.f);

    for (int c = 0; c < 18; c++) {
        const int jb = jb0 + c * 16;
        __syncthreads();
        for (int idx = t; idx < 2048; idx += ATTN_THREADS) {
            int jj = idx >> 7, dv = idx & 127;
            int j = jb + jj;
            float4 v = make_float4(0.f, 0.f, 0.f, 0.f);
            if (j >= 0 && j < SN) v = V4[(base + j) * 128 + dv];
            Vs4[jj * 128 + dv] = v;
        }
        __syncthreads();

        if (t < 256) {
            #pragma unroll 4
            for (int kj = 0; kj < 16; kj++) {
                float w0 = Ps[(2 * qp + 0) * PS_STRIDE + c * 16 + kj];
                float w1 = Ps[(2 * qp + 1) * PS_STRIDE + c * 16 + kj];
                #pragma unroll
                for (int dd = 0; dd < 8; dd++) {
                    float4 v = Vs4[kj * 128 + dl + 16 * dd];
                    av[0][dd].x += w0 * v.x; av[0][dd].y += w0 * v.y;
                    av[0][dd].z += w0 * v.z; av[0][dd].w += w0 * v.w;
                    av[1][dd].x += w1 * v.x; av[1][dd].y += w1 * v.y;
                    av[1][dd].z += w1 * v.z; av[1][dd].w += w1 * v.w;
                }
            }
        }
    }

    if (t < 256) {
        float4* O4 = (float4*)out;
        #pragma unroll
        for (int dd = 0; dd < 8; dd++) {
            O4[(base + q0 + 2 * qp + 0) * 128 + dl + 16 * dd] = av[0][dd];
            O4[(base + q0 + 2 * qp + 1) * 128 + dl + 16 * dd] = av[1][dd];
        }
    }
}

// ---------------------------------------------------------------------------
extern "C" void kernel_launch(void* const* d_in, const int* in_sizes, int n_in,
                              void* d_out, int out_size)
{
    const float* x  = (const float*)d_in[0];
    const float* Wq = (const float*)d_in[1];
    const float* bq = (const float*)d_in[2];
    const float* Wk = (const float*)d_in[3];
    const float* bk = (const float*)d_in[4];
    const float* Wv = (const float*)d_in[5];
    const float* bv = (const float*)d_in[6];
    float* out = (float*)d_out;

    cudaFuncSetAttribute(attn_kernel,
                         cudaFuncAttributeMaxDynamicSharedMemorySize, ATTN_SMEM);

    qkv_mma<<<dim3(MTOT / 128, 12), 256>>>(x, Wq, Wk, Wv, bq, bk, bv);
    attn_kernel<<<BN * (SN / TQ), ATTN_THREADS, ATTN_SMEM>>>(out);
}

// round 7
// speedup vs baseline: 4.3132x; 1.4684x over previous
#include <cuda_runtime.h>
#include <math.h>

#define BN 4
#define SN 4096
#define DN 512
#define MTOT (BN * SN)          // 16384
#define HALF_W 128
#define TQ 32
#define SPAN 288                // TQ + 2*HALF_W
#define PS_STRIDE 292           // 4 mod 32 -> conflict-free fragment access

// Scratch (no allocation allowed -> device globals)
__device__ float Qg[MTOT * DN];
__device__ float Kg[MTOT * DN];
__device__ float Vg[MTOT * DN];

// ---------------------------------------------------------------------------
// TF32 helpers
// ---------------------------------------------------------------------------
__device__ __forceinline__ unsigned f2tf(float f) {
    unsigned u;
    asm("cvt.rna.tf32.f32 %0, %1;" : "=r"(u) : "f"(f));
    return u;
}

__device__ __forceinline__ void mma_tf32(float* d, const unsigned* a, const unsigned* b) {
    asm volatile(
        "mma.sync.aligned.m16n8k8.row.col.f32.tf32.tf32.f32 "
        "{%0,%1,%2,%3}, {%4,%5,%6,%7}, {%8,%9}, {%0,%1,%2,%3};"
        : "+f"(d[0]), "+f"(d[1]), "+f"(d[2]), "+f"(d[3])
        : "r"(a[0]), "r"(a[1]), "r"(a[2]), "r"(a[3]),
          "r"(b[0]), "r"(b[1]));
}

// ---------------------------------------------------------------------------
// Kernel 1: QKV projection with TF32 tensor cores (unchanged, validated).
// ---------------------------------------------------------------------------
#define AS_STRIDE 36
#define BS_STRIDE 136

__global__ __launch_bounds__(256) void qkv_mma(
    const float* __restrict__ x,
    const float* __restrict__ Wq, const float* __restrict__ Wk, const float* __restrict__ Wv,
    const float* __restrict__ bq, const float* __restrict__ bk, const float* __restrict__ bv)
{
    __shared__ unsigned As[128 * AS_STRIDE];
    __shared__ unsigned Bs[32 * BS_STRIDE];

    const int t  = threadIdx.x;
    const int m0 = blockIdx.x * 128;
    const int yb = blockIdx.y;
    const int which = yb >> 2;
    const int n0 = (yb & 3) * 128;

    const float* W    = (which == 0) ? Wq : (which == 1) ? Wk : Wv;
    const float* bias = (which == 0) ? bq : (which == 1) ? bk : bv;
    float*       C    = (which == 0) ? Qg : (which == 1) ? Kg : Vg;

    const int warp = t >> 5, lane = t & 31;
    const int wm = (warp & 1) * 64;
    const int wn = (warp >> 1) * 32;
    const int gid = lane >> 2, tig = lane & 3;

    float d[4][4][4];
    #pragma unroll
    for (int mt = 0; mt < 4; mt++)
        #pragma unroll
        for (int nt = 0; nt < 4; nt++)
            #pragma unroll
            for (int r = 0; r < 4; r++) d[mt][nt][r] = 0.f;

    for (int k0 = 0; k0 < DN; k0 += 32) {
        __syncthreads();
        #pragma unroll
        for (int i = 0; i < 4; i++) {
            int idx = t + 256 * i;
            int m = idx >> 3, c = idx & 7;
            float4 v = *(const float4*)&x[(m0 + m) * DN + k0 + 4 * c];
            unsigned* p = &As[m * AS_STRIDE + 4 * c];
            p[0] = f2tf(v.x); p[1] = f2tf(v.y); p[2] = f2tf(v.z); p[3] = f2tf(v.w);
        }
        #pragma unroll
        for (int i = 0; i < 4; i++) {
            int idx = t + 256 * i;
            int k = idx >> 5, c = idx & 31;
            float4 v = *(const float4*)&W[(k0 + k) * DN + n0 + 4 * c];
            unsigned* p = &Bs[k * BS_STRIDE + 4 * c];
            p[0] = f2tf(v.x); p[1] = f2tf(v.y); p[2] = f2tf(v.z); p[3] = f2tf(v.w);
        }
        __syncthreads();

        #pragma unroll
        for (int kt = 0; kt < 4; kt++) {
            unsigned af[4][4], bf[4][2];
            #pragma unroll
            for (int mt = 0; mt < 4; mt++) {
                int r = wm + 16 * mt + gid;
                af[mt][0] = As[r * AS_STRIDE + 8 * kt + tig];
                af[mt][1] = As[(r + 8) * AS_STRIDE + 8 * kt + tig];
                af[mt][2] = As[r * AS_STRIDE + 8 * kt + 4 + tig];
                af[mt][3] = As[(r + 8) * AS_STRIDE + 8 * kt + 4 + tig];
            }
            #pragma unroll
            for (int nt = 0; nt < 4; nt++) {
                int cn = wn + 8 * nt + gid;
                bf[nt][0] = Bs[(8 * kt + tig) * BS_STRIDE + cn];
                bf[nt][1] = Bs[(8 * kt + 4 + tig) * BS_STRIDE + cn];
            }
            #pragma unroll
            for (int mt = 0; mt < 4; mt++)
                #pragma unroll
                for (int nt = 0; nt < 4; nt++)
                    mma_tf32(d[mt][nt], af[mt], bf[nt]);
        }
    }

    #pragma unroll
    for (int mt = 0; mt < 4; mt++) {
        int r = m0 + wm + 16 * mt + gid;
        #pragma unroll
        for (int nt = 0; nt < 4; nt++) {
            int cn = n0 + wn + 8 * nt + 2 * tig;
            float b0v = bias[cn], b1v = bias[cn + 1];
            float2 o0 = make_float2(d[mt][nt][0] + b0v, d[mt][nt][1] + b1v);
            float2 o1 = make_float2(d[mt][nt][2] + b0v, d[mt][nt][3] + b1v);
            *(float2*)&C[r * DN + cn]       = o0;
            *(float2*)&C[(r + 8) * DN + cn] = o1;
        }
    }
}

// ---------------------------------------------------------------------------
// Kernel 2: banded attention, all-mma. 288 threads (9 warps), 2 CTA/SM.
// smem layout (floats):
//   [0, 1152)       Qs [q=32][36]      (tf32 rna, scale pre-folded)
//   [1152, 11520)   Ks [key=288][36]   (raw fp32 bits; HW truncates to tf32)
//   [11520, 20864)  Ps [q=32][292]     (scores -> probs, tf32 rna)
// Phase 3 aliases Vs [key=32][264] = 33792 B at offset 0; Ps @46080 B safe.
// Phase 3 covers all 512 dims: 2 dim-groups x 256 dims, warps 0..7 own 32 each.
// ---------------------------------------------------------------------------
#define QS_STRIDE 36
#define KS_STRIDE 36
#define VS_STRIDE 264           // 8 mod 32 -> conflict-free b-frag reads
#define ATTN_THREADS 288
#define ATTN_SMEM ((1152 + 288 * KS_STRIDE + TQ * PS_STRIDE) * 4)   // 83456 B

__global__ __launch_bounds__(ATTN_THREADS, 2) void attn_kernel(float* __restrict__ out)
{
    extern __shared__ float sm[];
    float*    Qs  = sm;                               // [32][36]
    float*    Ks  = sm + 1152;                        // [288][36]
    float*    Ps  = sm + 1152 + 288 * KS_STRIDE;      // [32][292]
    unsigned* Qsu = (unsigned*)Qs;
    unsigned* Ksu = (unsigned*)Ks;
    unsigned* Psu = (unsigned*)Ps;
    unsigned* Vsu = (unsigned*)sm;                    // [32][264], phase 3 only

    const int t    = threadIdx.x;
    const int b    = blockIdx.x >> 7;
    const int tile = blockIdx.x & 127;
    const int q0   = tile * TQ;
    const int base = b * SN;
    const int jb0  = q0 - HALF_W;

    const float4* Q4 = (const float4*)Qg;
    const float4* K4 = (const float4*)Kg;
    const float4* V4 = (const float4*)Vg;

    const int warp = t >> 5, lane = t & 31;
    const int gid = lane >> 2, tig = lane & 3;
    const float scale = 0.044194173824159216f;   // 1/sqrt(512)

    // ---- Phase 1: S = Q K^T over 16 k-chunks of 32 dims (TF32 mma)
    float d[2][4][4];
    #pragma unroll
    for (int mt = 0; mt < 2; mt++)
        #pragma unroll
        for (int nf = 0; nf < 4; nf++)
            #pragma unroll
            for (int r = 0; r < 4; r++) d[mt][nf][r] = 0.f;

    for (int kc = 0; kc < 16; kc++) {
        __syncthreads();
        // Q chunk: scale folded, rna-rounded (tiny: 256 threads x 1 float4)
        if (t < 256) {
            int q = t >> 3, c = t & 7;
            float4 v = Q4[(base + q0 + q) * 128 + kc * 8 + c];
            unsigned* p = &Qsu[q * QS_STRIDE + 4 * c];
            p[0] = f2tf(v.x * scale); p[1] = f2tf(v.y * scale);
            p[2] = f2tf(v.z * scale); p[3] = f2tf(v.w * scale);
        }
        // K chunk: raw float4 copy (HW truncates mantissa), zero-fill OOB
        #pragma unroll
        for (int i = 0; i < 8; i++) {
            int idx = t + ATTN_THREADS * i;     // 0..2303
            int key = idx >> 3, c = idx & 7;
            int j = jb0 + key;
            float4 v = make_float4(0.f, 0.f, 0.f, 0.f);
            if (j >= 0 && j < SN) v = K4[(base + j) * 128 + kc * 8 + c];
            *(float4*)&Ks[key * KS_STRIDE + 4 * c] = v;
        }
        __syncthreads();

        #pragma unroll
        for (int kt = 0; kt < 4; kt++) {
            unsigned af[2][4], bf[4][2];
            #pragma unroll
            for (int mt = 0; mt < 2; mt++) {
                int r = 16 * mt + gid;
                af[mt][0] = Qsu[r * QS_STRIDE + 8 * kt + tig];
                af[mt][1] = Qsu[(r + 8) * QS_STRIDE + 8 * kt + tig];
                af[mt][2] = Qsu[r * QS_STRIDE + 8 * kt + 4 + tig];
                af[mt][3] = Qsu[(r + 8) * QS_STRIDE + 8 * kt + 4 + tig];
            }
            #pragma unroll
            for (int nf = 0; nf < 4; nf++) {
                int key = warp * 32 + 8 * nf + gid;
                bf[nf][0] = Ksu[key * KS_STRIDE + 8 * kt + tig];
                bf[nf][1] = Ksu[key * KS_STRIDE + 8 * kt + 4 + tig];
            }
            #pragma unroll
            for (int mt = 0; mt < 2; mt++)
                #pragma unroll
                for (int nf = 0; nf < 4; nf++)
                    mma_tf32(d[mt][nf], af[mt], bf[nf]);
        }
    }

    // Store scores (scale already folded into Q)
    #pragma unroll
    for (int mt = 0; mt < 2; mt++)
        #pragma unroll
        for (int nf = 0; nf < 4; nf++) {
            int col = warp * 32 + 8 * nf + 2 * tig;
            int r0 = 16 * mt + gid, r1 = r0 + 8;
            *(float2*)&Ps[r0 * PS_STRIDE + col] = make_float2(d[mt][nf][0], d[mt][nf][1]);
            *(float2*)&Ps[r1 * PS_STRIDE + col] = make_float2(d[mt][nf][2], d[mt][nf][3]);
        }
    __syncthreads();

    // ---- Phase 2: softmax per query row; final probs tf32-rounded (rna)
    for (int row = warp; row < TQ; row += 9) {
        const int lo = row, hi = row + 256;
        float m = -1e30f;
        #pragma unroll
        for (int tt = 0; tt < 9; tt++) {
            int kk = lane + tt * 32;
            int j = jb0 + kk;
            bool valid = (kk >= lo) && (kk <= hi) && (j >= 0) && (j < SN);
            float s = Ps[row * PS_STRIDE + kk];
            if (valid) m = fmaxf(m, s);
        }
        #pragma unroll
        for (int off = 16; off; off >>= 1)
            m = fmaxf(m, __shfl_xor_sync(0xffffffffu, m, off));
        float sum = 0.f;
        float pv[9];
        #pragma unroll
        for (int tt = 0; tt < 9; tt++) {
            int kk = lane + tt * 32;
            int j = jb0 + kk;
            bool valid = (kk >= lo) && (kk <= hi) && (j >= 0) && (j < SN);
            float p = valid ? __expf(Ps[row * PS_STRIDE + kk] - m) : 0.f;
            pv[tt] = p;
            sum += p;
        }
        #pragma unroll
        for (int off = 16; off; off >>= 1)
            sum += __shfl_xor_sync(0xffffffffu, sum, off);
        float inv = 1.f / sum;
        #pragma unroll
        for (int tt = 0; tt < 9; tt++) {
            int kk = lane + tt * 32;
            Psu[row * PS_STRIDE + kk] = f2tf(pv[tt] * inv);
        }
    }

    // ---- Phase 3: O = P @ V via TF32 mma. 2 dim-groups x 9 key chunks.
    // V natural [key][dim] supplies b-frags directly (contraction = V row).
    for (int dg = 0; dg < 2; dg++) {
        float d3[2][4][4];
        #pragma unroll
        for (int mt = 0; mt < 2; mt++)
            #pragma unroll
            for (int nt = 0; nt < 4; nt++)
                #pragma unroll
                for (int r = 0; r < 4; r++) d3[mt][nt][r] = 0.f;

        for (int c = 0; c < 9; c++) {
            const int jb = jb0 + c * 32;
            __syncthreads();
            // Stage V: 32 keys x 64 float4 (256 dims of group dg), rna-rounded
            #pragma unroll
            for (int i = 0; i < 8; i++) {
                int idx = t + ATTN_THREADS * i;     // 0..2303, need 2048
                if (idx < 2048) {
                    int key = idx >> 6, dq = idx & 63;
                    int j = jb + key;
                    float4 v = make_float4(0.f, 0.f, 0.f, 0.f);
                    if (j >= 0 && j < SN) v = V4[(base + j) * 128 + dg * 64 + dq];
                    unsigned* p = &Vsu[key * VS_STRIDE + 4 * dq];
                    p[0] = f2tf(v.x); p[1] = f2tf(v.y);
                    p[2] = f2tf(v.z); p[3] = f2tf(v.w);
                }
            }
            __syncthreads();

            if (warp < 8) {
                #pragma unroll
                for (int kt = 0; kt < 4; kt++) {
                    unsigned af[2][4], bf[4][2];
                    #pragma unroll
                    for (int mt = 0; mt < 2; mt++) {
                        int r = 16 * mt + gid;
                        int cb = c * 32 + 8 * kt;
                        af[mt][0] = Psu[r * PS_STRIDE + cb + tig];
                        af[mt][1] = Psu[(r + 8) * PS_STRIDE + cb + tig];
                        af[mt][2] = Psu[r * PS_STRIDE + cb + 4 + tig];
                        af[mt][3] = Psu[(r + 8) * PS_STRIDE + cb + 4 + tig];
                    }
                    #pragma unroll
                    for (int nt = 0; nt < 4; nt++) {
                        int cn = warp * 32 + 8 * nt + gid;
                        bf[nt][0] = Vsu[(8 * kt + tig) * VS_STRIDE + cn];
                        bf[nt][1] = Vsu[(8 * kt + 4 + tig) * VS_STRIDE + cn];
                    }
                    #pragma unroll
                    for (int mt = 0; mt < 2; mt++)
                        #pragma unroll
                        for (int nt = 0; nt < 4; nt++)
                            mma_tf32(d3[mt][nt], af[mt], bf[nt]);
                }
            }
        }

        if (warp < 8) {
            #pragma unroll
            for (int mt = 0; mt < 2; mt++) {
                int r0 = q0 + 16 * mt + gid;
                #pragma unroll
                for (int nt = 0; nt < 4; nt++) {
                    int cn = dg * 256 + warp * 32 + 8 * nt + 2 * tig;
                    *(float2*)&out[(base + r0) * DN + cn] =
                        make_float2(d3[mt][nt][0], d3[mt][nt][1]);
                    *(float2*)&out[(base + r0 + 8) * DN + cn] =
                        make_float2(d3[mt][nt][2], d3[mt][nt][3]);
                }
            }
        }
    }
}

// ---------------------------------------------------------------------------
extern "C" void kernel_launch(void* const* d_in, const int* in_sizes, int n_in,
                              void* d_out, int out_size)
{
    const float* x  = (const float*)d_in[0];
    const float* Wq = (const float*)d_in[1];
    const float* bq = (const float*)d_in[2];
    const float* Wk = (const float*)d_in[3];
    const float* bk = (const float*)d_in[4];
    const float* Wv = (const float*)d_in[5];
    const float* bv = (const float*)d_in[6];
    float* out = (float*)d_out;

    cudaFuncSetAttribute(attn_kernel,
                         cudaFuncAttributeMaxDynamicSharedMemorySize, ATTN_SMEM);

    qkv_mma<<<dim3(MTOT / 128, 12), 256>>>(x, Wq, Wk, Wv, bq, bk, bv);
    attn_kernel<<<BN * (SN / TQ), ATTN_THREADS, ATTN_SMEM>>>(out);
}